// round 15
// baseline (speedup 1.0000x reference)
#include <cuda_runtime.h>
#include <cuda_fp16.h>
#include <cstdint>

#define MTOK   8192
#define DMODEL 2048
#define DFF    8192
#define NGX    (DMODEL/64)
#define NGH    (DFF/64)
#define NWORDS ((DFF*DMODEL)/32)   // 524288 packed words per weight matrix

// ---------------- scratch (device globals; no allocations allowed) ----------
__device__ uint32_t g_w1b[NWORDS];
__device__ uint32_t g_w2b[NWORDS];
__device__ uint32_t g_w3b[NWORDS];
__device__ __half   g_xqh[MTOK*DMODEL];        // quantized x as exact fp16 integers
__device__ float    g_sx [MTOK*NGX];
__device__ __half   g_hqh[(size_t)MTOK*DFF];   // quantized h as exact fp16 integers
__device__ float    g_sh [MTOK*NGH];
__device__ float    g_partial[3][2048];
__device__ float    g_wscale[3];

// ---------------- small helpers --------------------------------------------
__device__ __forceinline__ void ldsm4(uint32_t r[4], uint32_t addr){
  asm volatile("ldmatrix.sync.aligned.m8n8.x4.shared.b16 {%0,%1,%2,%3},[%4];"
               : "=r"(r[0]),"=r"(r[1]),"=r"(r[2]),"=r"(r[3]) : "r"(addr));
}
__device__ __forceinline__ void hmma(float d[4], const uint32_t a[4], const uint32_t b[2]){
  asm volatile("mma.sync.aligned.m16n8k16.row.col.f32.f16.f16.f32 "
               "{%0,%1,%2,%3},{%4,%5,%6,%7},{%8,%9},{%0,%1,%2,%3};"
               : "+f"(d[0]),"+f"(d[1]),"+f"(d[2]),"+f"(d[3])
               : "r"(a[0]),"r"(a[1]),"r"(a[2]),"r"(a[3]),"r"(b[0]),"r"(b[1]));
}
__device__ __forceinline__ void cpa16(uint32_t d, const void* s){
  asm volatile("cp.async.cg.shared.global [%0],[%1],16;" :: "r"(d),"l"(s));
}
__device__ __forceinline__ void cpa4(uint32_t d, const void* s){
  asm volatile("cp.async.ca.shared.global [%0],[%1],4;" :: "r"(d),"l"(s));
}
__device__ __forceinline__ uint32_t lds32(uint32_t addr){
  uint32_t v; asm volatile("ld.shared.b32 %0,[%1];" : "=r"(v) : "r"(addr)); return v;
}

// ---------------- prep: pack sign bits (lane-owned words) + |w| partials -----
// Word t (global linear) decodes: inner=t&31 -> n07=inner>>2, c=inner&3;
// rest=t>>5 -> g = rest & (KG-1), nblk = rest >> log2(KG).   (KG = Kdim/64)
// Word covers cols n_a=nblk*16+n07 and n_b=n_a+8, sign bits for chunk g:
//  for ks in 0..3, with k = g*64+ks*16+2c:
//   n_a: w[k]<0 at bit ks,     w[k+1]<0 at 16+ks, w[k+8]<0 at 8+ks,  w[k+9]<0 at 24+ks
//   n_b: w[k]<0 at 4+ks,       w[k+1]<0 at 20+ks, w[k+8]<0 at 12+ks, w[k+9]<0 at 28+ks
__global__ void prep_pack(const float* __restrict__ w1, const float* __restrict__ w2,
                          const float* __restrict__ w3, uint32_t* __restrict__ b1,
                          uint32_t* __restrict__ b2, uint32_t* __restrict__ b3){
  const int idx = blockIdx.y;
  const float* __restrict__ w = (idx==0)?w1:((idx==1)?w2:w3);
  uint32_t* __restrict__ bits = (idx==0)?b1:((idx==1)?b2:b3);
  const int Kdim = (idx==2)? DFF : DMODEL;
  const int KG   = Kdim>>6;
  const int lgKG = (idx==2)? 7 : 5;

  int t = blockIdx.x*blockDim.x + threadIdx.x;   // exactly NWORDS threads
  int inner = t & 31;
  int n07 = inner>>2, c = inner&3;
  int rest = t>>5;
  int g    = rest & (KG-1);
  int nblk = rest >> lgKG;
  int n_a  = nblk*16 + n07;

  const float* ra = w + (size_t)n_a*Kdim;
  const float* rb = ra + (size_t)8*Kdim;

  float acc=0.f; uint32_t word=0;
#pragma unroll
  for (int ks=0;ks<4;ks++){
    int k0 = g*64 + ks*16 + 2*c;
    float2 va0 = *(const float2*)(ra + k0);
    float2 va1 = *(const float2*)(ra + k0 + 8);
    float2 vb0 = *(const float2*)(rb + k0);
    float2 vb1 = *(const float2*)(rb + k0 + 8);
    acc += fabsf(va0.x)+fabsf(va0.y)+fabsf(va1.x)+fabsf(va1.y)
         + fabsf(vb0.x)+fabsf(vb0.y)+fabsf(vb1.x)+fabsf(vb1.y);
    word |= ((uint32_t)(va0.x<0.f))<<ks       | ((uint32_t)(va0.y<0.f))<<(16+ks)
          | ((uint32_t)(va1.x<0.f))<<(8+ks)   | ((uint32_t)(va1.y<0.f))<<(24+ks)
          | ((uint32_t)(vb0.x<0.f))<<(4+ks)   | ((uint32_t)(vb0.y<0.f))<<(20+ks)
          | ((uint32_t)(vb1.x<0.f))<<(12+ks)  | ((uint32_t)(vb1.y<0.f))<<(28+ks);
  }
  bits[t]=word;

  __shared__ float sm[256];
  sm[threadIdx.x]=acc; __syncthreads();
  for (int s=128;s>0;s>>=1){ if(threadIdx.x<s) sm[threadIdx.x]+=sm[threadIdx.x+s]; __syncthreads(); }
  if (threadIdx.x==0) g_partial[idx][blockIdx.x]=sm[0];
}
__global__ void absmean_final3(float inv_n){
  __shared__ float sm[256];
  int idx=blockIdx.x; float s=0.f;
  for (int i=threadIdx.x;i<2048;i+=256) s+=g_partial[idx][i];
  sm[threadIdx.x]=s; __syncthreads();
  for (int t=128;t>0;t>>=1){ if(threadIdx.x<t) sm[threadIdx.x]+=sm[threadIdx.x+t]; __syncthreads(); }
  if (threadIdx.x==0) g_wscale[idx]=sm[0]*inv_n;
}

// ---------------- per-64-group quant: store integer q as exact fp16 ----------
__global__ void quant_kernel(const float2* __restrict__ src, __half2* __restrict__ q,
                             float* __restrict__ sc, int ngroups){
  int w=(blockIdx.x*blockDim.x+threadIdx.x)>>5, lane=threadIdx.x&31, nw=(gridDim.x*blockDim.x)>>5;
  for (int g=w; g<ngroups; g+=nw){
    float2 v = src[g*32+lane];
    float m = fmaxf(fabsf(v.x),fabsf(v.y));
#pragma unroll
    for (int o=16;o;o>>=1) m=fmaxf(m,__shfl_xor_sync(0xffffffffu,m,o));
    float s=fmaxf(m,1e-5f), inv=127.0f/s;
    float q0=(float)__float2int_rn(v.x*inv);
    float q1=(float)__float2int_rn(v.y*inv);
    q[g*32+lane]=__floats2half2_rn(q0,q1);
    if (lane==0) sc[g]=s*(1.0f/127.0f);
  }
}

// ---------------- grouped fp16 GEMM, bit-B, warp tile 64x16 ------------------
// CTA 128x128, 16 warps as 2(M)x8(N): wm=(wid>>3)*64, wn=(wid&7)*16. MT=4, NT=2.
// Each lane loads ONE packed word per chunk per pass; b-regs = SHL+LOP3 each.
// MODE 0: dual-B; epilogue SwiGLU + fused 64-col-group quant -> g_hqh,g_sh
// MODE 1: single-B; epilogue scale -> C
#define ATILE 16384    // 128 rows x 128 B (64 halves)

template<int MODE, int KTOT>
__global__ void __launch_bounds__(512,1) gemm_f16(
    const __half* __restrict__ A, const float* __restrict__ sA,
    const uint32_t* __restrict__ B1b, const uint32_t* __restrict__ B2b,
    float* __restrict__ C)
{
  constexpr int NB    = (MODE==0) ? 2 : 1;
  constexpr int KG    = KTOT/64;
  constexpr int NG    = KG;
  constexpr int STAGE = ATILE + NB*1024 + 512;
  extern __shared__ char smem[];
  const uint32_t sb = (uint32_t)__cvta_generic_to_shared(smem);
  const int tid = threadIdx.x, lane = tid&31, wid = tid>>5;
  const int m0 = blockIdx.y*128, n0 = blockIdx.x*128, nbb0 = blockIdx.x*8;
  const int wm = (wid>>3)*64, wn = (wid&7)*16;

  const int arow = lane&15;          // A row within m16
  const int acs  = lane>>4;          // A 16B-chunk select (k half)

  float f1[4][2][4]; float f2[4][2][4];
#pragma unroll
  for (int i=0;i<4;i++)
#pragma unroll
    for (int j=0;j<2;j++)
#pragma unroll
      for (int k=0;k<4;k++){ f1[i][j][k]=0.f; if (MODE==0) f2[i][j][k]=0.f; }

  auto load_stage = [&](uint32_t st, int g){
#pragma unroll
    for (int t=0;t<2;t++){
      int i = tid + t*512, r = i>>3, c = i&7;
      cpa16(st + r*128 + ((c ^ (r&7))<<4), A + (size_t)(m0+r)*KTOT + g*64 + c*8);
    }
    if (tid < 64*NB){
      int b = tid>>6, u = tid&63;
      const uint32_t* Bp = b ? B2b : B1b;
      cpa16(st + ATILE + b*1024 + (u>>3)*128 + (u&7)*16,
            Bp + ((size_t)(nbb0 + (u>>3))*KG + g)*32 + (u&7)*4);
    }
    if (tid >= 128 && tid < 256){
      int u = tid-128;
      cpa4(st + ATILE + NB*1024 + u*4, sA + (size_t)(m0+u)*KG + g);
    }
    asm volatile("cp.async.commit_group;");
  };

  load_stage(sb, 0);

#pragma unroll 1
  for (int g=0; g<NG; ++g){
    const int s = g&1;
    if (g+1 < NG){
      load_stage(sb + (s^1)*STAGE, g+1);
      asm volatile("cp.async.wait_group 1;");
    } else {
      asm volatile("cp.async.wait_group 0;");
    }
    __syncthreads();

    const uint32_t st = sb + s*STAGE;
    const float* sf = (const float*)(smem + s*STAGE + ATILE + NB*1024);
    float sc[4][2];
#pragma unroll
    for (int mt=0;mt<4;mt++){
      sc[mt][0] = sf[wm + mt*16 + (lane>>2)];
      sc[mt][1] = sf[wm + mt*16 + (lane>>2) + 8];
    }

    uint32_t Wb[NB];
    Wb[0] = lds32(st + ATILE + (wid&7)*128 + lane*4);
    if (MODE==0) Wb[1] = lds32(st + ATILE + 1024 + (wid&7)*128 + lane*4);

#pragma unroll
    for (int p=0; p<NB; ++p){
      const uint32_t W = Wb[p];
      float dt[4][2][4];
#pragma unroll
      for (int i=0;i<4;i++)
#pragma unroll
        for (int j=0;j<2;j++)
#pragma unroll
          for (int k=0;k<4;k++) dt[i][j][k]=0.f;

#pragma unroll
      for (int ks=0;ks<4;ks++){
        uint32_t a[4][4];
#pragma unroll
        for (int mt=0;mt<4;mt++){
          int row = wm + mt*16 + arow, c = ks*2 + acs;
          ldsm4(a[mt], st + row*128 + ((c ^ (row&7))<<4));
        }
        uint32_t b0[2], b1[2];
        b0[0] = ((W << (15-ks)) & 0x80008000u) | 0x3C003C00u;
        b0[1] = ((W << ( 7-ks)) & 0x80008000u) | 0x3C003C00u;
        b1[0] = ((W << (11-ks)) & 0x80008000u) | 0x3C003C00u;
        b1[1] = ((W << ( 3-ks)) & 0x80008000u) | 0x3C003C00u;
#pragma unroll
        for (int mt=0;mt<4;mt++){
          hmma(dt[mt][0], a[mt], b0);
          hmma(dt[mt][1], a[mt], b1);
        }
      }
      if (p==0){
#pragma unroll
        for (int mt=0;mt<4;mt++)
#pragma unroll
          for (int nt=0;nt<2;nt++){
            f1[mt][nt][0] += sc[mt][0]*dt[mt][nt][0];
            f1[mt][nt][1] += sc[mt][0]*dt[mt][nt][1];
            f1[mt][nt][2] += sc[mt][1]*dt[mt][nt][2];
            f1[mt][nt][3] += sc[mt][1]*dt[mt][nt][3];
          }
      } else {
#pragma unroll
        for (int mt=0;mt<4;mt++)
#pragma unroll
          for (int nt=0;nt<2;nt++){
            f2[mt][nt][0] += sc[mt][0]*dt[mt][nt][0];
            f2[mt][nt][1] += sc[mt][0]*dt[mt][nt][1];
            f2[mt][nt][2] += sc[mt][1]*dt[mt][nt][2];
            f2[mt][nt][3] += sc[mt][1]*dt[mt][nt][3];
          }
      }
    }
    __syncthreads();
  }

  // ---------------- epilogue ----------------
  if (MODE==0){
    // SwiGLU, then fused per-64-col quant. Group = 4 warps (16 cols each).
    float* smax = (float*)smem;                  // [2 grp][4 sub][128 rows] = 4KB
    const float c1=g_wscale[0], c2=g_wscale[1];
    const int grp = (wid>>2)&1, sub = wid&3;
    float rmax[4][2];
#pragma unroll
    for (int mt=0;mt<4;mt++)
#pragma unroll
      for (int hr=0;hr<2;hr++){
        float m=0.f;
#pragma unroll
        for (int nt=0;nt<2;nt++)
#pragma unroll
          for (int e=0;e<2;e++){
            float u=c1*f1[mt][nt][hr*2+e];
            float v=c2*f2[mt][nt][hr*2+e];
            float h=(u/(1.f+expf(-u)))*v;
            f1[mt][nt][hr*2+e]=h;
            m=fmaxf(m,fabsf(h));
          }
        m=fmaxf(m,__shfl_xor_sync(0xffffffffu,m,1));
        m=fmaxf(m,__shfl_xor_sync(0xffffffffu,m,2));
        rmax[mt][hr]=m;
      }
    if ((lane&3)==0){
#pragma unroll
      for (int mt=0;mt<4;mt++)
#pragma unroll
        for (int hr=0;hr<2;hr++){
          int rr=wm+mt*16+(lane>>2)+hr*8;
          smax[(grp*4+sub)*128+rr]=rmax[mt][hr];
        }
    }
    __syncthreads();
#pragma unroll
    for (int mt=0;mt<4;mt++)
#pragma unroll
      for (int hr=0;hr<2;hr++){
        int rr=wm+mt*16+(lane>>2)+hr*8;
        int row=m0+rr;
        float m = smax[(grp*4+0)*128+rr];
        m=fmaxf(m, smax[(grp*4+1)*128+rr]);
        m=fmaxf(m, smax[(grp*4+2)*128+rr]);
        m=fmaxf(m, smax[(grp*4+3)*128+rr]);
        float s=fmaxf(m,1e-5f), inv=127.0f/s;
#pragma unroll
        for (int nt=0;nt<2;nt++){
          float q0=(float)__float2int_rn(f1[mt][nt][hr*2+0]*inv);
          float q1=(float)__float2int_rn(f1[mt][nt][hr*2+1]*inv);
          *(__half2*)&g_hqh[(size_t)row*DFF + n0+wn+nt*8+(lane&3)*2] = __floats2half2_rn(q0,q1);
        }
        if (sub==0 && (lane&3)==0)
          g_sh[(size_t)row*NGH + (n0>>6)+grp]=s*(1.0f/127.0f);
      }
  } else {
    const float c3=g_wscale[2];
#pragma unroll
    for (int mt=0;mt<4;mt++)
#pragma unroll
      for (int nt=0;nt<2;nt++)
#pragma unroll
        for (int hr=0;hr<2;hr++){
          int row  = m0 + wm + mt*16 + (lane>>2) + hr*8;
          int cidx = n0 + wn + nt*8 + (lane&3)*2;
          *(float2*)&C[(size_t)row*DMODEL + cidx] =
              make_float2(c3*f1[mt][nt][hr*2+0], c3*f1[mt][nt][hr*2+1]);
        }
  }
}

// ---------------- host launcher ---------------------------------------------
extern "C" void kernel_launch(void* const* d_in, const int* in_sizes, int n_in,
                              void* d_out, int out_size)
{
  const float* x  = (const float*)d_in[0];
  const float* w1 = (const float*)d_in[1];
  const float* w2 = (const float*)d_in[2];
  const float* w3 = (const float*)d_in[3];

  void *w1b,*w2b,*w3b,*xq,*sx,*hq,*sh;
  cudaGetSymbolAddress(&w1b,g_w1b); cudaGetSymbolAddress(&w2b,g_w2b);
  cudaGetSymbolAddress(&w3b,g_w3b); cudaGetSymbolAddress(&xq ,g_xqh);
  cudaGetSymbolAddress(&sx ,g_sx ); cudaGetSymbolAddress(&hq ,g_hqh);
  cudaGetSymbolAddress(&sh ,g_sh );

  const int NW = DFF*DMODEL;       // 16.7M, same count for all three weights
  constexpr int SM0 = 2*(ATILE + 2*1024 + 512);   // 37888 B
  constexpr int SM1 = 2*(ATILE + 1*1024 + 512);   // 35840 B
  cudaFuncSetAttribute(gemm_f16<0,DMODEL>, cudaFuncAttributeMaxDynamicSharedMemorySize, SM0);
  cudaFuncSetAttribute(gemm_f16<1,DFF>,    cudaFuncAttributeMaxDynamicSharedMemorySize, SM1);

  // L1: pack sign bits (lane-owned layout) + abs-sum partials (all 3 weights)
  prep_pack<<<dim3(2048,3),256>>>(w1, w2, w3,
                                  (uint32_t*)w1b, (uint32_t*)w2b, (uint32_t*)w3b);
  // L2: quantize x (store exact integer q as fp16)
  quant_kernel<<<2048,256>>>((const float2*)x, (__half2*)xq, (float*)sx, MTOK*NGX);
  // L3: finalize weight scales
  absmean_final3<<<3,256>>>(1.0f/(float)NW);
  // L4: fused GEMM1+2 + SwiGLU + h-quant -> g_hqh/g_sh
  gemm_f16<0,DMODEL><<<dim3(DFF/128, MTOK/128), 512, SM0>>>(
      (const __half*)xq, (const float*)sx,
      (const uint32_t*)w1b, (const uint32_t*)w2b, nullptr);
  // L5: GEMM3 -> out
  gemm_f16<1,DFF><<<dim3(DMODEL/128, MTOK/128), 512, SM1>>>(
      (const __half*)hq, (const float*)sh,
      (const uint32_t*)w3b, nullptr, (float*)d_out);
}

// round 17
// speedup vs baseline: 1.4737x; 1.4737x over previous
#include <cuda_runtime.h>
#include <cuda_fp16.h>
#include <cstdint>

#define MTOK   8192
#define DMODEL 2048
#define DFF    8192
#define NGX    (DMODEL/64)
#define NGH    (DFF/64)
#define NWORDS ((DFF*DMODEL)/32)   // 524288 packed words per weight matrix

// ---------------- scratch (device globals; no allocations allowed) ----------
__device__ uint32_t g_w1b[NWORDS];
__device__ uint32_t g_w2b[NWORDS];
__device__ uint32_t g_w3b[NWORDS];
__device__ __half   g_xqh[MTOK*DMODEL];        // quantized x as exact fp16 integers
__device__ float    g_sx [MTOK*NGX];
__device__ __half   g_hqh[(size_t)MTOK*DFF];   // quantized h as exact fp16 integers
__device__ float    g_sh [MTOK*NGH];
__device__ float    g_partial[3][2048];
__device__ float    g_wscale[3];

// ---------------- small helpers --------------------------------------------
__device__ __forceinline__ void ldsm4(uint32_t r[4], uint32_t addr){
  asm volatile("ldmatrix.sync.aligned.m8n8.x4.shared.b16 {%0,%1,%2,%3},[%4];"
               : "=r"(r[0]),"=r"(r[1]),"=r"(r[2]),"=r"(r[3]) : "r"(addr));
}
__device__ __forceinline__ void hmma(float d[4], const uint32_t a[4], const uint32_t b[2]){
  asm volatile("mma.sync.aligned.m16n8k16.row.col.f32.f16.f16.f32 "
               "{%0,%1,%2,%3},{%4,%5,%6,%7},{%8,%9},{%0,%1,%2,%3};"
               : "+f"(d[0]),"+f"(d[1]),"+f"(d[2]),"+f"(d[3])
               : "r"(a[0]),"r"(a[1]),"r"(a[2]),"r"(a[3]),"r"(b[0]),"r"(b[1]));
}
__device__ __forceinline__ void cpa16(uint32_t d, const void* s){
  asm volatile("cp.async.cg.shared.global [%0],[%1],16;" :: "r"(d),"l"(s));
}
__device__ __forceinline__ void cpa4(uint32_t d, const void* s){
  asm volatile("cp.async.ca.shared.global [%0],[%1],4;" :: "r"(d),"l"(s));
}
__device__ __forceinline__ uint32_t lds32(uint32_t addr){
  uint32_t v; asm volatile("ld.shared.b32 %0,[%1];" : "=r"(v) : "r"(addr)); return v;
}

// ---------------- prep: pack sign bits (lane-owned words) + |w| partials -----
// Word t: inner=t&31 -> n07=inner>>2, c=inner&3; rest=t>>5 -> g=rest&(KG-1),
// nblk=rest>>log2(KG). Word covers cols n_a=nblk*16+n07 and n_b=n_a+8 for chunk g:
//  for ks in 0..3, k = g*64+ks*16+2c:
//   n_a: w[k]<0 at bit ks,  w[k+1]<0 at 16+ks, w[k+8]<0 at 8+ks,  w[k+9]<0 at 24+ks
//   n_b: w[k]<0 at 4+ks,    w[k+1]<0 at 20+ks, w[k+8]<0 at 12+ks, w[k+9]<0 at 28+ks
__global__ void prep_pack(const float* __restrict__ w1, const float* __restrict__ w2,
                          const float* __restrict__ w3, uint32_t* __restrict__ b1,
                          uint32_t* __restrict__ b2, uint32_t* __restrict__ b3){
  const int idx = blockIdx.y;
  const float* __restrict__ w = (idx==0)?w1:((idx==1)?w2:w3);
  uint32_t* __restrict__ bits = (idx==0)?b1:((idx==1)?b2:b3);
  const int Kdim = (idx==2)? DFF : DMODEL;
  const int KG   = Kdim>>6;
  const int lgKG = (idx==2)? 7 : 5;

  int t = blockIdx.x*blockDim.x + threadIdx.x;   // exactly NWORDS threads
  int inner = t & 31;
  int n07 = inner>>2, c = inner&3;
  int rest = t>>5;
  int g    = rest & (KG-1);
  int nblk = rest >> lgKG;
  int n_a  = nblk*16 + n07;

  const float* ra = w + (size_t)n_a*Kdim;
  const float* rb = ra + (size_t)8*Kdim;

  float acc=0.f; uint32_t word=0;
#pragma unroll
  for (int ks=0;ks<4;ks++){
    int k0 = g*64 + ks*16 + 2*c;
    float2 va0 = *(const float2*)(ra + k0);
    float2 va1 = *(const float2*)(ra + k0 + 8);
    float2 vb0 = *(const float2*)(rb + k0);
    float2 vb1 = *(const float2*)(rb + k0 + 8);
    acc += fabsf(va0.x)+fabsf(va0.y)+fabsf(va1.x)+fabsf(va1.y)
         + fabsf(vb0.x)+fabsf(vb0.y)+fabsf(vb1.x)+fabsf(vb1.y);
    word |= ((uint32_t)(va0.x<0.f))<<ks       | ((uint32_t)(va0.y<0.f))<<(16+ks)
          | ((uint32_t)(va1.x<0.f))<<(8+ks)   | ((uint32_t)(va1.y<0.f))<<(24+ks)
          | ((uint32_t)(vb0.x<0.f))<<(4+ks)   | ((uint32_t)(vb0.y<0.f))<<(20+ks)
          | ((uint32_t)(vb1.x<0.f))<<(12+ks)  | ((uint32_t)(vb1.y<0.f))<<(28+ks);
  }
  bits[t]=word;

  __shared__ float sm[256];
  sm[threadIdx.x]=acc; __syncthreads();
  for (int s=128;s>0;s>>=1){ if(threadIdx.x<s) sm[threadIdx.x]+=sm[threadIdx.x+s]; __syncthreads(); }
  if (threadIdx.x==0) g_partial[idx][blockIdx.x]=sm[0];
}
__global__ void absmean_final3(float inv_n){
  __shared__ float sm[256];
  int idx=blockIdx.x; float s=0.f;
  for (int i=threadIdx.x;i<2048;i+=256) s+=g_partial[idx][i];
  sm[threadIdx.x]=s; __syncthreads();
  for (int t=128;t>0;t>>=1){ if(threadIdx.x<t) sm[threadIdx.x]+=sm[threadIdx.x+t]; __syncthreads(); }
  if (threadIdx.x==0) g_wscale[idx]=sm[0]*inv_n;
}

// ---------------- per-64-group quant: store integer q as exact fp16 ----------
__global__ void quant_kernel(const float2* __restrict__ src, __half2* __restrict__ q,
                             float* __restrict__ sc, int ngroups){
  int w=(blockIdx.x*blockDim.x+threadIdx.x)>>5, lane=threadIdx.x&31, nw=(gridDim.x*blockDim.x)>>5;
  for (int g=w; g<ngroups; g+=nw){
    float2 v = src[g*32+lane];
    float m = fmaxf(fabsf(v.x),fabsf(v.y));
#pragma unroll
    for (int o=16;o;o>>=1) m=fmaxf(m,__shfl_xor_sync(0xffffffffu,m,o));
    float s=fmaxf(m,1e-5f), inv=127.0f/s;
    float q0=(float)__float2int_rn(v.x*inv);
    float q1=(float)__float2int_rn(v.y*inv);
    q[g*32+lane]=__floats2half2_rn(q0,q1);
    if (lane==0) sc[g]=s*(1.0f/127.0f);
  }
}

// ---------------- grouped fp16 GEMM, bit-B, R13 tiles + cheap synthesis ------
// CTA 128x128, 16 warps as 4(M)x4(N): wm=(wid>>2)*32, wn=(wid&3)*32. MT=2, NT=4.
// Warp spans 2 16-col bit-blocks; 2 LDS + (SHL+LOP3)x8 per chunk per pass.
// MODE 0: dual-B; epilogue SwiGLU + fused 64-col-group quant -> g_hqh,g_sh
// MODE 1: single-B; epilogue scale -> C
#define ATILE 16384    // 128 rows x 128 B (64 halves)

template<int MODE, int KTOT>
__global__ void __launch_bounds__(512,1) gemm_f16(
    const __half* __restrict__ A, const float* __restrict__ sA,
    const uint32_t* __restrict__ B1b, const uint32_t* __restrict__ B2b,
    float* __restrict__ C)
{
  constexpr int NB    = (MODE==0) ? 2 : 1;
  constexpr int KG    = KTOT/64;
  constexpr int NG    = KG;
  constexpr int STAGE = ATILE + NB*1024 + 512;
  extern __shared__ char smem[];
  const uint32_t sb = (uint32_t)__cvta_generic_to_shared(smem);
  const int tid = threadIdx.x, lane = tid&31, wid = tid>>5;
  const int m0 = blockIdx.y*128, n0 = blockIdx.x*128, nbb0 = blockIdx.x*8;
  const int wm = (wid>>2)*32, wn = (wid&3)*32;

  const int arow = lane&15;          // A row within m16
  const int acs  = lane>>4;          // A 16B-chunk select (k half)

  float f1[2][4][4]; float f2[2][4][4];
#pragma unroll
  for (int i=0;i<2;i++)
#pragma unroll
    for (int j=0;j<4;j++)
#pragma unroll
      for (int k=0;k<4;k++){ f1[i][j][k]=0.f; if (MODE==0) f2[i][j][k]=0.f; }

  auto load_stage = [&](uint32_t st, int g){
#pragma unroll
    for (int t=0;t<2;t++){
      int i = tid + t*512, r = i>>3, c = i&7;
      cpa16(st + r*128 + ((c ^ (r&7))<<4), A + (size_t)(m0+r)*KTOT + g*64 + c*8);
    }
    if (tid < 64*NB){
      int b = tid>>6, u = tid&63;
      const uint32_t* Bp = b ? B2b : B1b;
      cpa16(st + ATILE + b*1024 + (u>>3)*128 + (u&7)*16,
            Bp + ((size_t)(nbb0 + (u>>3))*KG + g)*32 + (u&7)*4);
    }
    if (tid >= 128 && tid < 256){
      int u = tid-128;
      cpa4(st + ATILE + NB*1024 + u*4, sA + (size_t)(m0+u)*KG + g);
    }
    asm volatile("cp.async.commit_group;");
  };

  load_stage(sb, 0);

#pragma unroll 1
  for (int g=0; g<NG; ++g){
    const int s = g&1;
    if (g+1 < NG){
      load_stage(sb + (s^1)*STAGE, g+1);
      asm volatile("cp.async.wait_group 1;");
    } else {
      asm volatile("cp.async.wait_group 0;");
    }
    __syncthreads();

    const uint32_t st = sb + s*STAGE;
    const float* sf = (const float*)(smem + s*STAGE + ATILE + NB*1024);
    float sc[2][2];
#pragma unroll
    for (int mt=0;mt<2;mt++){
      sc[mt][0] = sf[wm + mt*16 + (lane>>2)];
      sc[mt][1] = sf[wm + mt*16 + (lane>>2) + 8];
    }

    // lane-owned packed words: 2 per pass (warp spans 2 16-col blocks)
    uint32_t W0[NB], W1[NB];
    {
      uint32_t base = st + ATILE + (uint32_t)(wid&3)*256 + (uint32_t)lane*4;
      W0[0] = lds32(base);
      W1[0] = lds32(base + 128);
      if (MODE==0){ W0[1] = lds32(base + 1024); W1[1] = lds32(base + 1024 + 128); }
    }

#pragma unroll
    for (int p=0; p<NB; ++p){
      float dt[2][4][4];
#pragma unroll
      for (int i=0;i<2;i++)
#pragma unroll
        for (int j=0;j<4;j++)
#pragma unroll
          for (int k=0;k<4;k++) dt[i][j][k]=0.f;

#pragma unroll
      for (int ks=0;ks<4;ks++){
        uint32_t a[2][4];
#pragma unroll
        for (int mt=0;mt<2;mt++){
          int row = wm + mt*16 + arow, c = ks*2 + acs;
          ldsm4(a[mt], st + row*128 + ((c ^ (row&7))<<4));
        }
        uint32_t b[4][2];
        b[0][0] = ((W0[p] << (15-ks)) & 0x80008000u) | 0x3C003C00u;
        b[0][1] = ((W0[p] << ( 7-ks)) & 0x80008000u) | 0x3C003C00u;
        b[1][0] = ((W0[p] << (11-ks)) & 0x80008000u) | 0x3C003C00u;
        b[1][1] = ((W0[p] << ( 3-ks)) & 0x80008000u) | 0x3C003C00u;
        b[2][0] = ((W1[p] << (15-ks)) & 0x80008000u) | 0x3C003C00u;
        b[2][1] = ((W1[p] << ( 7-ks)) & 0x80008000u) | 0x3C003C00u;
        b[3][0] = ((W1[p] << (11-ks)) & 0x80008000u) | 0x3C003C00u;
        b[3][1] = ((W1[p] << ( 3-ks)) & 0x80008000u) | 0x3C003C00u;
#pragma unroll
        for (int mt=0;mt<2;mt++)
#pragma unroll
          for (int nt=0;nt<4;nt++) hmma(dt[mt][nt], a[mt], b[nt]);
      }
      if (p==0){
#pragma unroll
        for (int mt=0;mt<2;mt++)
#pragma unroll
          for (int nt=0;nt<4;nt++){
            f1[mt][nt][0] += sc[mt][0]*dt[mt][nt][0];
            f1[mt][nt][1] += sc[mt][0]*dt[mt][nt][1];
            f1[mt][nt][2] += sc[mt][1]*dt[mt][nt][2];
            f1[mt][nt][3] += sc[mt][1]*dt[mt][nt][3];
          }
      } else {
#pragma unroll
        for (int mt=0;mt<2;mt++)
#pragma unroll
          for (int nt=0;nt<4;nt++){
            f2[mt][nt][0] += sc[mt][0]*dt[mt][nt][0];
            f2[mt][nt][1] += sc[mt][0]*dt[mt][nt][1];
            f2[mt][nt][2] += sc[mt][1]*dt[mt][nt][2];
            f2[mt][nt][3] += sc[mt][1]*dt[mt][nt][3];
          }
      }
    }
    __syncthreads();
  }

  // ---------------- epilogue ----------------
  if (MODE==0){
    // SwiGLU, then fused per-64-col quant. Quant group = warp pair (wn, wn^32).
    float* smax = (float*)smem;                  // [grp(2)][half(2)][row(128)]
    const float c1=g_wscale[0], c2=g_wscale[1];
    const int grp = wn>>6, halfw=(wn>>5)&1;
    float rmax[2][2];
#pragma unroll
    for (int mt=0;mt<2;mt++)
#pragma unroll
      for (int hr=0;hr<2;hr++){
        float m=0.f;
#pragma unroll
        for (int nt=0;nt<4;nt++)
#pragma unroll
          for (int e=0;e<2;e++){
            float u=c1*f1[mt][nt][hr*2+e];
            float v=c2*f2[mt][nt][hr*2+e];
            float h=(u/(1.f+expf(-u)))*v;
            f1[mt][nt][hr*2+e]=h;
            m=fmaxf(m,fabsf(h));
          }
        m=fmaxf(m,__shfl_xor_sync(0xffffffffu,m,1));
        m=fmaxf(m,__shfl_xor_sync(0xffffffffu,m,2));
        rmax[mt][hr]=m;
      }
    if ((lane&3)==0){
#pragma unroll
      for (int mt=0;mt<2;mt++)
#pragma unroll
        for (int hr=0;hr<2;hr++){
          int rr=wm+mt*16+(lane>>2)+hr*8;
          smax[(grp*2+halfw)*128+rr]=rmax[mt][hr];
        }
    }
    __syncthreads();
#pragma unroll
    for (int mt=0;mt<2;mt++)
#pragma unroll
      for (int hr=0;hr<2;hr++){
        int rr=wm+mt*16+(lane>>2)+hr*8;
        int row=m0+rr;
        float m=fmaxf(rmax[mt][hr], smax[(grp*2+(halfw^1))*128+rr]);
        float s=fmaxf(m,1e-5f), inv=127.0f/s;
#pragma unroll
        for (int nt=0;nt<4;nt++){
          float q0=(float)__float2int_rn(f1[mt][nt][hr*2+0]*inv);
          float q1=(float)__float2int_rn(f1[mt][nt][hr*2+1]*inv);
          *(__half2*)&g_hqh[(size_t)row*DFF + n0+wn+nt*8+(lane&3)*2] = __floats2half2_rn(q0,q1);
        }
        if (halfw==0 && (lane&3)==0)
          g_sh[(size_t)row*NGH + (n0>>6)+grp]=s*(1.0f/127.0f);
      }
  } else {
    const float c3=g_wscale[2];
#pragma unroll
    for (int mt=0;mt<2;mt++)
#pragma unroll
      for (int nt=0;nt<4;nt++)
#pragma unroll
        for (int hr=0;hr<2;hr++){
          int row  = m0 + wm + mt*16 + (lane>>2) + hr*8;
          int cidx = n0 + wn + nt*8 + (lane&3)*2;
          *(float2*)&C[(size_t)row*DMODEL + cidx] =
              make_float2(c3*f1[mt][nt][hr*2+0], c3*f1[mt][nt][hr*2+1]);
        }
  }
}

// ---------------- host launcher ---------------------------------------------
extern "C" void kernel_launch(void* const* d_in, const int* in_sizes, int n_in,
                              void* d_out, int out_size)
{
  const float* x  = (const float*)d_in[0];
  const float* w1 = (const float*)d_in[1];
  const float* w2 = (const float*)d_in[2];
  const float* w3 = (const float*)d_in[3];

  void *w1b,*w2b,*w3b,*xq,*sx,*hq,*sh;
  cudaGetSymbolAddress(&w1b,g_w1b); cudaGetSymbolAddress(&w2b,g_w2b);
  cudaGetSymbolAddress(&w3b,g_w3b); cudaGetSymbolAddress(&xq ,g_xqh);
  cudaGetSymbolAddress(&sx ,g_sx ); cudaGetSymbolAddress(&hq ,g_hqh);
  cudaGetSymbolAddress(&sh ,g_sh );

  const int NW = DFF*DMODEL;       // 16.7M, same count for all three weights
  constexpr int SM0 = 2*(ATILE + 2*1024 + 512);   // 37888 B
  constexpr int SM1 = 2*(ATILE + 1*1024 + 512);   // 35840 B
  cudaFuncSetAttribute(gemm_f16<0,DMODEL>, cudaFuncAttributeMaxDynamicSharedMemorySize, SM0);
  cudaFuncSetAttribute(gemm_f16<1,DFF>,    cudaFuncAttributeMaxDynamicSharedMemorySize, SM1);

  // L1: pack sign bits (lane-owned layout) + abs-sum partials (all 3 weights)
  prep_pack<<<dim3(2048,3),256>>>(w1, w2, w3,
                                  (uint32_t*)w1b, (uint32_t*)w2b, (uint32_t*)w3b);
  // L2: quantize x (store exact integer q as fp16)
  quant_kernel<<<2048,256>>>((const float2*)x, (__half2*)xq, (float*)sx, MTOK*NGX);
  // L3: finalize weight scales
  absmean_final3<<<3,256>>>(1.0f/(float)NW);
  // L4: fused GEMM1+2 + SwiGLU + h-quant -> g_hqh/g_sh
  gemm_f16<0,DMODEL><<<dim3(DFF/128, MTOK/128), 512, SM0>>>(
      (const __half*)xq, (const float*)sx,
      (const uint32_t*)w1b, (const uint32_t*)w2b, nullptr);
  // L5: GEMM3 -> out
  gemm_f16<1,DFF><<<dim3(DMODEL/128, MTOK/128), 512, SM1>>>(
      (const __half*)hq, (const float*)sh,
      (const uint32_t*)w3b, nullptr, (float*)d_out);
}